// round 12
// baseline (speedup 1.0000x reference)
#include <cuda_runtime.h>
#include <cuda_bf16.h>
#include <cuda_fp16.h>
#include <math.h>

// Problem constants
#define NB 8
#define NL 2048
#define ND 512
#define BLD (NB*NL*ND)              // 8,388,608 elems per tensor
#define BLL_ ((long long)NB*NL*NL)  // 33,554,432 per direction score matrix

// Scratch (device globals: allocation-free per harness rules)
__device__ unsigned short g_hbf[2ULL*BLD];        // h_s, h_c bf16
__device__ unsigned short g_wbf[8ULL*512*512];    // weights bf16
__device__ unsigned short g_qb[2ULL*BLD];
__device__ unsigned short g_kb[2ULL*BLD];
__device__ unsigned short g_vb[2ULL*BLD];
__device__ unsigned short g_gb[2ULL*BLD];
__device__ unsigned short g_s [2ULL*BLL_];        // fp16 scores
__device__ unsigned short g_pb[2ULL*BLL_];        // bf16 probs

// ---------------------------------------------------------------------------
// PTX helpers (sm_90-era, compile on plain sm_103 target)
// ---------------------------------------------------------------------------
__device__ __forceinline__ unsigned smem_u32(const void* p) {
    return (unsigned)__cvta_generic_to_shared(p);
}
__device__ __forceinline__ void cp16(unsigned dst, const void* src) {
    asm volatile("cp.async.cg.shared.global [%0], [%1], 16;\n" :: "r"(dst), "l"(src));
}
__device__ __forceinline__ void cp_commit() { asm volatile("cp.async.commit_group;\n"); }
template<int N> __device__ __forceinline__ void cp_wait() {
    asm volatile("cp.async.wait_group %0;\n" :: "n"(N));
}
__device__ __forceinline__ void ldsm4(unsigned* r, unsigned a) {
    asm volatile("ldmatrix.sync.aligned.m8n8.x4.shared.b16 {%0,%1,%2,%3}, [%4];\n"
        : "=r"(r[0]), "=r"(r[1]), "=r"(r[2]), "=r"(r[3]) : "r"(a));
}
__device__ __forceinline__ void ldsm4t(unsigned* r, unsigned a) {
    asm volatile("ldmatrix.sync.aligned.m8n8.x4.trans.shared.b16 {%0,%1,%2,%3}, [%4];\n"
        : "=r"(r[0]), "=r"(r[1]), "=r"(r[2]), "=r"(r[3]) : "r"(a));
}
__device__ __forceinline__ void mma16816(float* c, const unsigned* a, const unsigned* b) {
    asm volatile("mma.sync.aligned.m16n8k16.row.col.f32.bf16.bf16.f32 "
        "{%0,%1,%2,%3}, {%4,%5,%6,%7}, {%8,%9}, {%0,%1,%2,%3};\n"
        : "+f"(c[0]), "+f"(c[1]), "+f"(c[2]), "+f"(c[3])
        : "r"(a[0]), "r"(a[1]), "r"(a[2]), "r"(a[3]), "r"(b[0]), "r"(b[1]));
}
__device__ __forceinline__ unsigned short f2bfu(float x) {
    return __bfloat16_as_ushort(__float2bfloat16_rn(x));
}
__device__ __forceinline__ float bfu2f(unsigned short u) {
    return __bfloat162float(__ushort_as_bfloat16(u));
}

// ---------------------------------------------------------------------------
// bf16 tensor-core GEMM body (mma.sync), fp32 accumulate. Pointers pre-offset.
//   BT = true : C[m,n] = alpha*sum_k A[m,k]*B[n,k] (+bias[n])  "NT", B is NxK
//   BT = false: C[m,n] = alpha*sum_k A[m,k]*B[k,n]             "NN", B is KxN
//   OUT: 1=bf16, 2=f16, 3=fused finalize: out = H + sigmoid(G)*acc (f32)
// CTA tile 128x128x64, 128 threads = 4 warps (2x2), warp tile 64x64.
// 3-stage cp.async ring, ONE __syncthreads per 64-k slab, 2 CTAs/SM.
// Rolling 2-deep fragment pipeline across the 4 microsteps; B via ldsm x4.
// ---------------------------------------------------------------------------
template<bool BT, int OUT>
__device__ __forceinline__ void gemm_body(
    unsigned short* sm,
    const unsigned short* __restrict__ A,
    const unsigned short* __restrict__ Bm,
    const float* __restrict__ bias, void* __restrict__ Cv,
    int N, int K, float alpha,
    const float* __restrict__ Hres,
    const unsigned short* __restrict__ Gpre)
{
    constexpr int LDA = 72;                    // 64 + 8 pad (elems)
    constexpr int ASZ = 128 * LDA;             // 9216 elems
    constexpr int LDB = BT ? 72 : 136;         // NT: [128][72], NN: [64][136]
    constexpr int BSZ = BT ? 128 * 72 : 64 * 136;
    constexpr int STG = ASZ + BSZ;             // elems per stage

    const int tid  = threadIdx.x;
    const int lane = tid & 31;
    const int wid  = tid >> 5;
    const int warpM = wid >> 1;                // 0..1 (64 rows)
    const int warpN = wid & 1;                 // 0..1 (64 cols)
    const int rowBase = blockIdx.y * 128;
    const int colBase = blockIdx.x * 128;

    float acc[4][8][4];
    #pragma unroll
    for (int i = 0; i < 4; i++)
        #pragma unroll
        for (int j = 0; j < 8; j++)
            #pragma unroll
            for (int e = 0; e < 4; e++) acc[i][j][e] = 0.f;

    const unsigned smb = smem_u32(sm);

    auto load_stage = [&](int f) {
        const int s = f % 3;
        const int k0 = f * 64;
        const unsigned sa = smb + (unsigned)(s * STG) * 2u;
        const unsigned sb = sa + (unsigned)ASZ * 2u;
        // A: 128 rows x 64 cols, 8x16B per row, 1024 chunks, 8/thread
        #pragma unroll
        for (int i = 0; i < 8; i++) {
            int c = i * 128 + tid;
            int row = c >> 3, seg = c & 7;
            cp16(sa + (unsigned)(row * LDA + seg * 8) * 2u,
                 A + (long long)(rowBase + row) * K + k0 + seg * 8);
        }
        if (BT) {  // B NxK: 128 rows x 64 cols
            #pragma unroll
            for (int i = 0; i < 8; i++) {
                int c = i * 128 + tid;
                int row = c >> 3, seg = c & 7;
                cp16(sb + (unsigned)(row * LDB + seg * 8) * 2u,
                     Bm + (long long)(colBase + row) * K + k0 + seg * 8);
            }
        } else {   // B KxN: 64 rows x 128 cols
            #pragma unroll
            for (int i = 0; i < 8; i++) {
                int c = i * 128 + tid;
                int row = c >> 4, seg = c & 15;
                cp16(sb + (unsigned)(row * LDB + seg * 8) * 2u,
                     Bm + (long long)(k0 + row) * N + colBase + seg * 8);
            }
        }
    };

    // Fragment load for one 16-k microstep (ks in {0,16,32,48}).
    auto ldfrag = [&](unsigned sa, unsigned sb, int ks,
                      unsigned (&a)[4][4], unsigned (&b)[8][2]) {
        #pragma unroll
        for (int mi = 0; mi < 4; mi++) {
            int row = warpM * 64 + mi * 16 + (lane & 7) + (lane & 8);
            int col = ks + ((lane & 16) >> 1);
            ldsm4(a[mi], sa + (unsigned)(row * LDA + col) * 2u);
        }
        #pragma unroll
        for (int ni = 0; ni < 8; ni += 2) {
            if (BT) {
                // x4: m0=(ni,k-lo) m1=(ni,k-hi) m2=(ni+1,k-lo) m3=(ni+1,k-hi)
                int row = warpN * 64 + (ni + ((lane >> 4) & 1)) * 8 + (lane & 7);
                int col = ks + (lane & 8);
                ldsm4(&b[ni][0], sb + (unsigned)(row * LDB + col) * 2u);
            } else {
                // x4 trans: rows = k, cols = n
                int row = ks + (lane & 15);
                int col = warpN * 64 + (ni + ((lane >> 4) & 1)) * 8;
                ldsm4t(&b[ni][0], sb + (unsigned)(row * LDB + col) * 2u);
            }
        }
    };

    auto compute_stage = [&](int kt) {
        const int s = kt % 3;
        const unsigned sa = smb + (unsigned)(s * STG) * 2u;
        const unsigned sb = sa + (unsigned)ASZ * 2u;
        unsigned a[2][4][4], b[2][8][2];
        ldfrag(sa, sb, 0, a[0], b[0]);
        #pragma unroll
        for (int ms = 0; ms < 4; ms++) {
            if (ms + 1 < 4) ldfrag(sa, sb, (ms + 1) * 16, a[(ms + 1) & 1], b[(ms + 1) & 1]);
            #pragma unroll
            for (int mi = 0; mi < 4; mi++)
                #pragma unroll
                for (int ni = 0; ni < 8; ni++)
                    mma16816(acc[mi][ni], a[ms & 1][mi], b[ms & 1][ni]);
        }
    };

    const int nk = K / 64;

    load_stage(0); cp_commit();
    load_stage(1); cp_commit();

    for (int kt = 0; kt < nk; kt++) {
        if (kt + 2 <= nk) cp_wait<1>(); else cp_wait<0>();
        __syncthreads();
        if (kt + 2 < nk) { load_stage(kt + 2); cp_commit(); }
        compute_stage(kt);
    }

    // Epilogue
    const int rr = lane >> 2, cc = (lane & 3) << 1;
    #pragma unroll
    for (int mi = 0; mi < 4; mi++) {
        const int row0 = rowBase + warpM * 64 + mi * 16 + rr;
        #pragma unroll
        for (int ni = 0; ni < 8; ni++) {
            const int col = colBase + warpN * 64 + ni * 8 + cc;
            const long long offA = (long long)row0 * N + col;
            const long long offB = (long long)(row0 + 8) * N + col;
            if (OUT == 3) {
                float* Cf = (float*)Cv;
                float2 hA = *(const float2*)&Hres[offA];
                float2 hB = *(const float2*)&Hres[offB];
                unsigned gA = *(const unsigned*)&Gpre[offA];
                unsigned gB = *(const unsigned*)&Gpre[offB];
                float g0 = bfu2f((unsigned short)(gA & 0xffff));
                float g1 = bfu2f((unsigned short)(gA >> 16));
                float g2 = bfu2f((unsigned short)(gB & 0xffff));
                float g3 = bfu2f((unsigned short)(gB >> 16));
                float2 oA, oB;
                oA.x = hA.x + acc[mi][ni][0] / (1.f + __expf(-g0));
                oA.y = hA.y + acc[mi][ni][1] / (1.f + __expf(-g1));
                oB.x = hB.x + acc[mi][ni][2] / (1.f + __expf(-g2));
                oB.y = hB.y + acc[mi][ni][3] / (1.f + __expf(-g3));
                *(float2*)&Cf[offA] = oA;
                *(float2*)&Cf[offB] = oB;
            } else {
                float b0 = 0.f, b1 = 0.f;
                if (bias) { b0 = bias[col]; b1 = bias[col + 1]; }
                float x0 = alpha * acc[mi][ni][0] + b0;
                float x1 = alpha * acc[mi][ni][1] + b1;
                float x2 = alpha * acc[mi][ni][2] + b0;
                float x3 = alpha * acc[mi][ni][3] + b1;
                if (OUT == 1) {
                    unsigned short* Cb = (unsigned short*)Cv;
                    *(unsigned*)&Cb[offA] = (unsigned)f2bfu(x0) | ((unsigned)f2bfu(x1) << 16);
                    *(unsigned*)&Cb[offB] = (unsigned)f2bfu(x2) | ((unsigned)f2bfu(x3) << 16);
                } else {
                    unsigned short* Ch = (unsigned short*)Cv;
                    __half2 h0 = __floats2half2_rn(x0, x1);
                    __half2 h1 = __floats2half2_rn(x2, x3);
                    *(unsigned*)&Ch[offA] = *(unsigned*)&h0;
                    *(unsigned*)&Ch[offB] = *(unsigned*)&h1;
                }
            }
        }
    }
}

// Dynamic smem sizes (bytes)
#define DSM_NT ((128*72 + 128*72) * 3 * 2)   // 110592
#define DSM_NN ((128*72 + 64*136) * 3 * 2)   // 107520

// ---------------------------------------------------------------------------
// Batched kernels (one launch per phase)
// ---------------------------------------------------------------------------
struct ProjArgs {
    const unsigned short* A[8];
    const unsigned short* W[8];
    const float*          bias[8];
    unsigned short*       C[8];
};

__global__ __launch_bounds__(128, 2)
void proj_k(ProjArgs pa)
{
    extern __shared__ __align__(16) unsigned short sm[];
    const int z = blockIdx.z;
    gemm_body<true, 1>(sm, pa.A[z], pa.W[z], pa.bias[z], pa.C[z],
                       ND, ND, 1.f, nullptr, nullptr);
}

__global__ __launch_bounds__(128, 2)
void qk_k(const unsigned short* __restrict__ Q,
          const unsigned short* __restrict__ Kb,
          unsigned short* __restrict__ S, float alpha)
{
    extern __shared__ __align__(16) unsigned short sm[];
    const int z = blockIdx.z;   // 0..15
    gemm_body<true, 2>(sm,
                       Q + (long long)z * NL * ND,
                       Kb + (long long)z * NL * ND,
                       nullptr,
                       S + (long long)z * NL * NL,
                       NL, ND, alpha, nullptr, nullptr);
}

__global__ __launch_bounds__(128, 2)
void pv_k(const unsigned short* __restrict__ P,
          const unsigned short* __restrict__ V,
          const float* __restrict__ h_s, const float* __restrict__ h_c,
          const unsigned short* __restrict__ G, float* __restrict__ out)
{
    extern __shared__ __align__(16) unsigned short sm[];
    const int z = blockIdx.z;   // 0..15: 0-7 dir0 (h_s), 8-15 dir1 (h_c)
    const float* H = (z < 8) ? (h_s + (long long)z * NL * ND)
                             : (h_c + (long long)(z - 8) * NL * ND);
    gemm_body<false, 3>(sm,
                        P + (long long)z * NL * NL,
                        V + (long long)z * NL * ND,
                        nullptr,
                        out + (long long)z * NL * ND,
                        ND, NL, 1.f, H,
                        G + (long long)z * NL * ND);
}

// ---------------------------------------------------------------------------
// fp32 -> bf16 conversions, batched
// ---------------------------------------------------------------------------
__global__ void f2bf_in_k(const float4* __restrict__ a, const float4* __restrict__ b,
                          uint2* __restrict__ out)
{
    const long long i = (long long)blockIdx.x * 256 + threadIdx.x;
    const float4* in = blockIdx.z ? b : a;
    float4 v = in[i];
    uint2 o;
    o.x = (unsigned)f2bfu(v.x) | ((unsigned)f2bfu(v.y) << 16);
    o.y = (unsigned)f2bfu(v.z) | ((unsigned)f2bfu(v.w) << 16);
    out[(long long)blockIdx.z * (BLD/4) + i] = o;
}

struct WPtrs { const float4* W[8]; };

__global__ void f2bf_w_k(WPtrs wp, uint2* __restrict__ out)
{
    const int i = blockIdx.x * 256 + threadIdx.x;
    float4 v = wp.W[blockIdx.z][i];
    uint2 o;
    o.x = (unsigned)f2bfu(v.x) | ((unsigned)f2bfu(v.y) << 16);
    o.y = (unsigned)f2bfu(v.z) | ((unsigned)f2bfu(v.w) << 16);
    out[(long long)blockIdx.z * (512*512/4) + i] = o;
}

// ---------------------------------------------------------------------------
// Row softmax: fp16 scores in, bf16 probs out. One 256-thread CTA per row
// of 2048 (each thread owns 8 contiguous halves = one uint4).
// ---------------------------------------------------------------------------
__global__ void softmax_k(const uint4* __restrict__ S, uint4* __restrict__ P)
{
    const long long base = (long long)blockIdx.x * 256;
    const int tid = threadIdx.x;
    uint4 c = S[base + tid];
    float v[8];
    {
        __half2 h; float2 f;
        *(unsigned*)&h = c.x; f = __half22float2(h); v[0] = f.x; v[1] = f.y;
        *(unsigned*)&h = c.y; f = __half22float2(h); v[2] = f.x; v[3] = f.y;
        *(unsigned*)&h = c.z; f = __half22float2(h); v[4] = f.x; v[5] = f.y;
        *(unsigned*)&h = c.w; f = __half22float2(h); v[6] = f.x; v[7] = f.y;
    }
    float m = v[0];
    #pragma unroll
    for (int j = 1; j < 8; j++) m = fmaxf(m, v[j]);
    float s = 0.f;
    #pragma unroll
    for (int j = 0; j < 8; j++) s += __expf(v[j] - m);

    #pragma unroll
    for (int o = 16; o; o >>= 1) {
        float om = __shfl_xor_sync(0xffffffffu, m, o);
        float os = __shfl_xor_sync(0xffffffffu, s, o);
        float nm = fmaxf(m, om);
        s = s * __expf(m - nm) + os * __expf(om - nm);
        m = nm;
    }
    __shared__ float smx[8], ssx[8];
    if ((tid & 31) == 0) { smx[tid >> 5] = m; ssx[tid >> 5] = s; }
    __syncthreads();
    float M = smx[0], Ssum = ssx[0];
    #pragma unroll
    for (int w = 1; w < 8; w++) {
        float om = smx[w], os = ssx[w];
        float nm = fmaxf(M, om);
        Ssum = Ssum * __expf(M - nm) + os * __expf(om - nm);
        M = nm;
    }
    const float inv = 1.f / Ssum;

    unsigned short e[8];
    #pragma unroll
    for (int j = 0; j < 8; j++) e[j] = f2bfu(__expf(v[j] - M) * inv);
    uint4 o;
    o.x = (unsigned)e[0] | ((unsigned)e[1] << 16);
    o.y = (unsigned)e[2] | ((unsigned)e[3] << 16);
    o.z = (unsigned)e[4] | ((unsigned)e[5] << 16);
    o.w = (unsigned)e[6] | ((unsigned)e[7] << 16);
    P[base + tid] = o;
}

// ---------------------------------------------------------------------------
// kernel_launch
// Inputs: h_s, h_c, then (W,b) for qs, kc, vc, qc, ks, vs, gs, gc.
// ---------------------------------------------------------------------------
extern "C" void kernel_launch(void* const* d_in, const int* in_sizes, int n_in,
                              void* d_out, int out_size)
{
    (void)in_sizes; (void)n_in; (void)out_size;
    const float* h_s = (const float*)d_in[0];
    const float* h_c = (const float*)d_in[1];
    const float* W[8]; const float* bia[8];
    for (int i = 0; i < 8; i++) { W[i] = (const float*)d_in[2 + 2*i]; bia[i] = (const float*)d_in[3 + 2*i]; }
    // order: 0=qs 1=kc 2=vc 3=qc 4=ks 5=vs 6=gs 7=gc
    float* out = (float*)d_out;

    unsigned short *hbf, *wbf, *qb, *kb, *vb, *gb, *pb, *s;
    cudaGetSymbolAddress((void**)&hbf, g_hbf);
    cudaGetSymbolAddress((void**)&wbf, g_wbf);
    cudaGetSymbolAddress((void**)&qb,  g_qb);
    cudaGetSymbolAddress((void**)&kb,  g_kb);
    cudaGetSymbolAddress((void**)&vb,  g_vb);
    cudaGetSymbolAddress((void**)&gb,  g_gb);
    cudaGetSymbolAddress((void**)&pb,  g_pb);
    cudaGetSymbolAddress((void**)&s,   g_s);

    const int M = NB * NL;      // 16384
    const long long WSZ = 512 * 512;

    cudaFuncSetAttribute(proj_k, cudaFuncAttributeMaxDynamicSharedMemorySize, DSM_NT);
    cudaFuncSetAttribute(qk_k,   cudaFuncAttributeMaxDynamicSharedMemorySize, DSM_NT);
    cudaFuncSetAttribute(pv_k,   cudaFuncAttributeMaxDynamicSharedMemorySize, DSM_NN);

    // Conversions: 2 launches (inputs z=2, weights z=8)
    {
        dim3 gi(BLD/4/256, 1, 2);
        f2bf_in_k<<<gi, 256>>>((const float4*)h_s, (const float4*)h_c, (uint2*)hbf);
        WPtrs wp;
        for (int i = 0; i < 8; i++) wp.W[i] = (const float4*)W[i];
        dim3 gw(WSZ/4/256, 1, 8);
        f2bf_w_k<<<gw, 256>>>(wp, (uint2*)wbf);
    }

    const unsigned short* hsb = hbf;
    const unsigned short* hcb = hbf + BLD;

    // Phase 1: all 8 projections in ONE launch (grid.z selects)
    {
        ProjArgs pa;
        const unsigned short* As[8] = { hsb, hcb, hcb, hsb, hcb, hsb, hsb, hcb };
        const int widx[8]           = {  0,   1,   2,   6,   3,   4,   5,   7 };
        unsigned short* Cs[8] = { qb, kb, vb, gb, qb+BLD, kb+BLD, vb+BLD, gb+BLD };
        for (int i = 0; i < 8; i++) {
            pa.A[i]    = As[i];
            pa.W[i]    = wbf + (long long)widx[i] * WSZ;
            pa.bias[i] = bia[widx[i]];
            pa.C[i]    = Cs[i];
        }
        dim3 gp(ND/128, M/128, 8), blk(128);
        proj_k<<<gp, blk, DSM_NT>>>(pa);
    }

    // Phase 2a: scores = alpha * Q @ K^T (NT, fp16 out), one launch z=16
    {
        const float alpha = 1.0f / sqrtf((float)ND);
        dim3 gq(NL/128, NL/128, 16), blk(128);
        qk_k<<<gq, blk, DSM_NT>>>(qb, kb, s, alpha);
    }

    // Phase 2b: softmax fp16 -> bf16 probs (32768 rows)
    softmax_k<<<16*NL, 256>>>((const uint4*)s, (uint4*)pb);

    // Phase 2c+3 fused: out = h + sigmoid(g) * (P @ V), one launch z=16
    {
        dim3 gc(ND/128, NL/128, 16), blk(128);
        pv_k<<<gc, blk, DSM_NN>>>(pb, vb, h_s, h_c, gb, out);
    }
}

// round 13
// speedup vs baseline: 1.0728x; 1.0728x over previous
#include <cuda_runtime.h>
#include <cuda_bf16.h>
#include <cuda_fp16.h>
#include <math.h>

// Problem constants
#define NB 8
#define NL 2048
#define ND 512
#define BLD (NB*NL*ND)              // 8,388,608 elems per tensor
#define BLL_ ((long long)NB*NL*NL)  // 33,554,432 per direction score matrix

// Scratch (device globals: allocation-free per harness rules)
__device__ unsigned short g_hbf[2ULL*BLD];        // h_s, h_c bf16
__device__ unsigned short g_wbf[8ULL*512*512];    // weights bf16
__device__ unsigned short g_qb[2ULL*BLD];
__device__ unsigned short g_kb[2ULL*BLD];
__device__ unsigned short g_vb[2ULL*BLD];
__device__ unsigned short g_gb[2ULL*BLD];
__device__ unsigned short g_s [2ULL*BLL_];        // fp16 scores
__device__ unsigned short g_pb[2ULL*BLL_];        // bf16 probs

// ---------------------------------------------------------------------------
// PTX helpers (sm_90-era, compile on plain sm_103 target)
// ---------------------------------------------------------------------------
__device__ __forceinline__ unsigned smem_u32(const void* p) {
    return (unsigned)__cvta_generic_to_shared(p);
}
__device__ __forceinline__ void cp16(unsigned dst, const void* src) {
    asm volatile("cp.async.cg.shared.global [%0], [%1], 16;\n" :: "r"(dst), "l"(src));
}
__device__ __forceinline__ void cp_commit() { asm volatile("cp.async.commit_group;\n"); }
template<int N> __device__ __forceinline__ void cp_wait() {
    asm volatile("cp.async.wait_group %0;\n" :: "n"(N));
}
__device__ __forceinline__ void ldsm4(unsigned* r, unsigned a) {
    asm volatile("ldmatrix.sync.aligned.m8n8.x4.shared.b16 {%0,%1,%2,%3}, [%4];\n"
        : "=r"(r[0]), "=r"(r[1]), "=r"(r[2]), "=r"(r[3]) : "r"(a));
}
__device__ __forceinline__ void ldsm4t(unsigned* r, unsigned a) {
    asm volatile("ldmatrix.sync.aligned.m8n8.x4.trans.shared.b16 {%0,%1,%2,%3}, [%4];\n"
        : "=r"(r[0]), "=r"(r[1]), "=r"(r[2]), "=r"(r[3]) : "r"(a));
}
__device__ __forceinline__ void mma16816(float* c, const unsigned* a, const unsigned* b) {
    asm volatile("mma.sync.aligned.m16n8k16.row.col.f32.bf16.bf16.f32 "
        "{%0,%1,%2,%3}, {%4,%5,%6,%7}, {%8,%9}, {%0,%1,%2,%3};\n"
        : "+f"(c[0]), "+f"(c[1]), "+f"(c[2]), "+f"(c[3])
        : "r"(a[0]), "r"(a[1]), "r"(a[2]), "r"(a[3]), "r"(b[0]), "r"(b[1]));
}
__device__ __forceinline__ unsigned short f2bfu(float x) {
    return __bfloat16_as_ushort(__float2bfloat16_rn(x));
}
__device__ __forceinline__ float bfu2f(unsigned short u) {
    return __bfloat162float(__ushort_as_bfloat16(u));
}

// ---------------------------------------------------------------------------
// bf16 tensor-core GEMM body (mma.sync), fp32 accumulate. Pointers pre-offset.
//   BT = true : C[m,n] = alpha*sum_k A[m,k]*B[n,k] (+bias[n])  "NT", B is NxK
//   BT = false: C[m,n] = alpha*sum_k A[m,k]*B[k,n]             "NN", B is KxN
//   OUT: 1=bf16, 2=f16, 3=fused finalize: out = H + sigmoid(G)*acc (f32)
// CTA tile 128x128x32, 128 threads = 4 warps (2x2), warp tile 64x64.
// 3-stage cp.async ring, ONE __syncthreads per 32-k slab, 3 CTAs/SM.
// Single-buffered fragments (register budget for occupancy 3).
// ---------------------------------------------------------------------------
template<bool BT, int OUT>
__device__ __forceinline__ void gemm_body(
    unsigned short* sm,
    const unsigned short* __restrict__ A,
    const unsigned short* __restrict__ Bm,
    const float* __restrict__ bias, void* __restrict__ Cv,
    int N, int K, float alpha,
    const float* __restrict__ Hres,
    const unsigned short* __restrict__ Gpre)
{
    constexpr int LDA = 40;                    // 32 + 8 pad (elems)
    constexpr int ASZ = 128 * LDA;             // 5120 elems
    constexpr int LDB = BT ? 40 : 136;         // NT: [128][40], NN: [32][136]
    constexpr int BSZ = BT ? 128 * 40 : 32 * 136;
    constexpr int STG = ASZ + BSZ;             // elems per stage

    const int tid  = threadIdx.x;
    const int lane = tid & 31;
    const int wid  = tid >> 5;
    const int warpM = wid >> 1;                // 0..1 (64 rows)
    const int warpN = wid & 1;                 // 0..1 (64 cols)
    const int rowBase = blockIdx.y * 128;
    const int colBase = blockIdx.x * 128;

    float acc[4][8][4];
    #pragma unroll
    for (int i = 0; i < 4; i++)
        #pragma unroll
        for (int j = 0; j < 8; j++)
            #pragma unroll
            for (int e = 0; e < 4; e++) acc[i][j][e] = 0.f;

    const unsigned smb = smem_u32(sm);

    auto load_stage = [&](int f) {
        const int s = f % 3;
        const int k0 = f * 32;
        const unsigned sa = smb + (unsigned)(s * STG) * 2u;
        const unsigned sb = sa + (unsigned)ASZ * 2u;
        // A: 128 rows x 32 cols, 4x16B per row, 512 chunks, 4/thread
        #pragma unroll
        for (int i = 0; i < 4; i++) {
            int c = i * 128 + tid;
            int row = c >> 2, seg = c & 3;
            cp16(sa + (unsigned)(row * LDA + seg * 8) * 2u,
                 A + (long long)(rowBase + row) * K + k0 + seg * 8);
        }
        if (BT) {  // B NxK: 128 rows x 32 cols
            #pragma unroll
            for (int i = 0; i < 4; i++) {
                int c = i * 128 + tid;
                int row = c >> 2, seg = c & 3;
                cp16(sb + (unsigned)(row * LDB + seg * 8) * 2u,
                     Bm + (long long)(colBase + row) * K + k0 + seg * 8);
            }
        } else {   // B KxN: 32 rows x 128 cols
            #pragma unroll
            for (int i = 0; i < 4; i++) {
                int c = i * 128 + tid;
                int row = c >> 4, seg = c & 15;
                cp16(sb + (unsigned)(row * LDB + seg * 8) * 2u,
                     Bm + (long long)(k0 + row) * N + colBase + seg * 8);
            }
        }
    };

    // Fragment load for one 16-k microstep (ks in {0,16}).
    auto ldfrag = [&](unsigned sa, unsigned sb, int ks,
                      unsigned (&a)[4][4], unsigned (&b)[8][2]) {
        #pragma unroll
        for (int mi = 0; mi < 4; mi++) {
            int row = warpM * 64 + mi * 16 + (lane & 7) + (lane & 8);
            int col = ks + ((lane & 16) >> 1);
            ldsm4(a[mi], sa + (unsigned)(row * LDA + col) * 2u);
        }
        #pragma unroll
        for (int ni = 0; ni < 8; ni += 2) {
            if (BT) {
                // x4: m0=(ni,k-lo) m1=(ni,k-hi) m2=(ni+1,k-lo) m3=(ni+1,k-hi)
                int row = warpN * 64 + (ni + ((lane >> 4) & 1)) * 8 + (lane & 7);
                int col = ks + (lane & 8);
                ldsm4(&b[ni][0], sb + (unsigned)(row * LDB + col) * 2u);
            } else {
                // x4 trans: rows = k, cols = n
                int row = ks + (lane & 15);
                int col = warpN * 64 + (ni + ((lane >> 4) & 1)) * 8;
                ldsm4t(&b[ni][0], sb + (unsigned)(row * LDB + col) * 2u);
            }
        }
    };

    auto compute_stage = [&](int kt) {
        const int s = kt % 3;
        const unsigned sa = smb + (unsigned)(s * STG) * 2u;
        const unsigned sb = sa + (unsigned)ASZ * 2u;
        #pragma unroll
        for (int ms = 0; ms < 2; ms++) {
            unsigned a[4][4], b[8][2];
            ldfrag(sa, sb, ms * 16, a, b);
            #pragma unroll
            for (int mi = 0; mi < 4; mi++)
                #pragma unroll
                for (int ni = 0; ni < 8; ni++)
                    mma16816(acc[mi][ni], a[mi], b[ni]);
        }
    };

    const int nk = K / 32;

    load_stage(0); cp_commit();
    load_stage(1); cp_commit();

    for (int kt = 0; kt < nk; kt++) {
        if (kt + 2 <= nk) cp_wait<1>(); else cp_wait<0>();
        __syncthreads();
        if (kt + 2 < nk) { load_stage(kt + 2); cp_commit(); }
        compute_stage(kt);
    }

    // Epilogue
    const int rr = lane >> 2, cc = (lane & 3) << 1;
    #pragma unroll
    for (int mi = 0; mi < 4; mi++) {
        const int row0 = rowBase + warpM * 64 + mi * 16 + rr;
        #pragma unroll
        for (int ni = 0; ni < 8; ni++) {
            const int col = colBase + warpN * 64 + ni * 8 + cc;
            const long long offA = (long long)row0 * N + col;
            const long long offB = (long long)(row0 + 8) * N + col;
            if (OUT == 3) {
                float* Cf = (float*)Cv;
                float2 hA = *(const float2*)&Hres[offA];
                float2 hB = *(const float2*)&Hres[offB];
                unsigned gA = *(const unsigned*)&Gpre[offA];
                unsigned gB = *(const unsigned*)&Gpre[offB];
                float g0 = bfu2f((unsigned short)(gA & 0xffff));
                float g1 = bfu2f((unsigned short)(gA >> 16));
                float g2 = bfu2f((unsigned short)(gB & 0xffff));
                float g3 = bfu2f((unsigned short)(gB >> 16));
                float2 oA, oB;
                oA.x = hA.x + acc[mi][ni][0] / (1.f + __expf(-g0));
                oA.y = hA.y + acc[mi][ni][1] / (1.f + __expf(-g1));
                oB.x = hB.x + acc[mi][ni][2] / (1.f + __expf(-g2));
                oB.y = hB.y + acc[mi][ni][3] / (1.f + __expf(-g3));
                *(float2*)&Cf[offA] = oA;
                *(float2*)&Cf[offB] = oB;
            } else {
                float b0 = 0.f, b1 = 0.f;
                if (bias) { b0 = bias[col]; b1 = bias[col + 1]; }
                float x0 = alpha * acc[mi][ni][0] + b0;
                float x1 = alpha * acc[mi][ni][1] + b1;
                float x2 = alpha * acc[mi][ni][2] + b0;
                float x3 = alpha * acc[mi][ni][3] + b1;
                if (OUT == 1) {
                    unsigned short* Cb = (unsigned short*)Cv;
                    *(unsigned*)&Cb[offA] = (unsigned)f2bfu(x0) | ((unsigned)f2bfu(x1) << 16);
                    *(unsigned*)&Cb[offB] = (unsigned)f2bfu(x2) | ((unsigned)f2bfu(x3) << 16);
                } else {
                    unsigned short* Ch = (unsigned short*)Cv;
                    __half2 h0 = __floats2half2_rn(x0, x1);
                    __half2 h1 = __floats2half2_rn(x2, x3);
                    *(unsigned*)&Ch[offA] = *(unsigned*)&h0;
                    *(unsigned*)&Ch[offB] = *(unsigned*)&h1;
                }
            }
        }
    }
}

// Dynamic smem sizes (bytes)
#define DSM_NT ((128*40 + 128*40) * 3 * 2)   // 61440
#define DSM_NN ((128*40 + 32*136) * 3 * 2)   // 56832

// ---------------------------------------------------------------------------
// Batched kernels (one launch per phase)
// ---------------------------------------------------------------------------
struct ProjArgs {
    const unsigned short* A[8];
    const unsigned short* W[8];
    const float*          bias[8];
    unsigned short*       C[8];
};

__global__ __launch_bounds__(128, 3)
void proj_k(ProjArgs pa)
{
    extern __shared__ __align__(16) unsigned short sm[];
    const int z = blockIdx.z;
    gemm_body<true, 1>(sm, pa.A[z], pa.W[z], pa.bias[z], pa.C[z],
                       ND, ND, 1.f, nullptr, nullptr);
}

__global__ __launch_bounds__(128, 3)
void qk_k(const unsigned short* __restrict__ Q,
          const unsigned short* __restrict__ Kb,
          unsigned short* __restrict__ S, float alpha)
{
    extern __shared__ __align__(16) unsigned short sm[];
    const int z = blockIdx.z;   // 0..15
    gemm_body<true, 2>(sm,
                       Q + (long long)z * NL * ND,
                       Kb + (long long)z * NL * ND,
                       nullptr,
                       S + (long long)z * NL * NL,
                       NL, ND, alpha, nullptr, nullptr);
}

__global__ __launch_bounds__(128, 3)
void pv_k(const unsigned short* __restrict__ P,
          const unsigned short* __restrict__ V,
          const float* __restrict__ h_s, const float* __restrict__ h_c,
          const unsigned short* __restrict__ G, float* __restrict__ out)
{
    extern __shared__ __align__(16) unsigned short sm[];
    const int z = blockIdx.z;   // 0..15: 0-7 dir0 (h_s), 8-15 dir1 (h_c)
    const float* H = (z < 8) ? (h_s + (long long)z * NL * ND)
                             : (h_c + (long long)(z - 8) * NL * ND);
    gemm_body<false, 3>(sm,
                        P + (long long)z * NL * NL,
                        V + (long long)z * NL * ND,
                        nullptr,
                        out + (long long)z * NL * ND,
                        ND, NL, 1.f, H,
                        G + (long long)z * NL * ND);
}

// ---------------------------------------------------------------------------
// fp32 -> bf16 conversions, batched
// ---------------------------------------------------------------------------
__global__ void f2bf_in_k(const float4* __restrict__ a, const float4* __restrict__ b,
                          uint2* __restrict__ out)
{
    const long long i = (long long)blockIdx.x * 256 + threadIdx.x;
    const float4* in = blockIdx.z ? b : a;
    float4 v = in[i];
    uint2 o;
    o.x = (unsigned)f2bfu(v.x) | ((unsigned)f2bfu(v.y) << 16);
    o.y = (unsigned)f2bfu(v.z) | ((unsigned)f2bfu(v.w) << 16);
    out[(long long)blockIdx.z * (BLD/4) + i] = o;
}

struct WPtrs { const float4* W[8]; };

__global__ void f2bf_w_k(WPtrs wp, uint2* __restrict__ out)
{
    const int i = blockIdx.x * 256 + threadIdx.x;
    float4 v = wp.W[blockIdx.z][i];
    uint2 o;
    o.x = (unsigned)f2bfu(v.x) | ((unsigned)f2bfu(v.y) << 16);
    o.y = (unsigned)f2bfu(v.z) | ((unsigned)f2bfu(v.w) << 16);
    out[(long long)blockIdx.z * (512*512/4) + i] = o;
}

// ---------------------------------------------------------------------------
// Row softmax: fp16 scores in, bf16 probs out. One 256-thread CTA per row
// of 2048 (each thread owns 8 contiguous halves = one uint4).
// ---------------------------------------------------------------------------
__global__ void softmax_k(const uint4* __restrict__ S, uint4* __restrict__ P)
{
    const long long base = (long long)blockIdx.x * 256;
    const int tid = threadIdx.x;
    uint4 c = S[base + tid];
    float v[8];
    {
        __half2 h; float2 f;
        *(unsigned*)&h = c.x; f = __half22float2(h); v[0] = f.x; v[1] = f.y;
        *(unsigned*)&h = c.y; f = __half22float2(h); v[2] = f.x; v[3] = f.y;
        *(unsigned*)&h = c.z; f = __half22float2(h); v[4] = f.x; v[5] = f.y;
        *(unsigned*)&h = c.w; f = __half22float2(h); v[6] = f.x; v[7] = f.y;
    }
    float m = v[0];
    #pragma unroll
    for (int j = 1; j < 8; j++) m = fmaxf(m, v[j]);
    float s = 0.f;
    #pragma unroll
    for (int j = 0; j < 8; j++) s += __expf(v[j] - m);

    #pragma unroll
    for (int o = 16; o; o >>= 1) {
        float om = __shfl_xor_sync(0xffffffffu, m, o);
        float os = __shfl_xor_sync(0xffffffffu, s, o);
        float nm = fmaxf(m, om);
        s = s * __expf(m - nm) + os * __expf(om - nm);
        m = nm;
    }
    __shared__ float smx[8], ssx[8];
    if ((tid & 31) == 0) { smx[tid >> 5] = m; ssx[tid >> 5] = s; }
    __syncthreads();
    float M = smx[0], Ssum = ssx[0];
    #pragma unroll
    for (int w = 1; w < 8; w++) {
        float om = smx[w], os = ssx[w];
        float nm = fmaxf(M, om);
        Ssum = Ssum * __expf(M - nm) + os * __expf(om - nm);
        M = nm;
    }
    const float inv = 1.f / Ssum;

    unsigned short e[8];
    #pragma unroll
    for (int j = 0; j < 8; j++) e[j] = f2bfu(__expf(v[j] - M) * inv);
    uint4 o;
    o.x = (unsigned)e[0] | ((unsigned)e[1] << 16);
    o.y = (unsigned)e[2] | ((unsigned)e[3] << 16);
    o.z = (unsigned)e[4] | ((unsigned)e[5] << 16);
    o.w = (unsigned)e[6] | ((unsigned)e[7] << 16);
    P[base + tid] = o;
}

// ---------------------------------------------------------------------------
// kernel_launch
// Inputs: h_s, h_c, then (W,b) for qs, kc, vc, qc, ks, vs, gs, gc.
// ---------------------------------------------------------------------------
extern "C" void kernel_launch(void* const* d_in, const int* in_sizes, int n_in,
                              void* d_out, int out_size)
{
    (void)in_sizes; (void)n_in; (void)out_size;
    const float* h_s = (const float*)d_in[0];
    const float* h_c = (const float*)d_in[1];
    const float* W[8]; const float* bia[8];
    for (int i = 0; i < 8; i++) { W[i] = (const float*)d_in[2 + 2*i]; bia[i] = (const float*)d_in[3 + 2*i]; }
    // order: 0=qs 1=kc 2=vc 3=qc 4=ks 5=vs 6=gs 7=gc
    float* out = (float*)d_out;

    unsigned short *hbf, *wbf, *qb, *kb, *vb, *gb, *pb, *s;
    cudaGetSymbolAddress((void**)&hbf, g_hbf);
    cudaGetSymbolAddress((void**)&wbf, g_wbf);
    cudaGetSymbolAddress((void**)&qb,  g_qb);
    cudaGetSymbolAddress((void**)&kb,  g_kb);
    cudaGetSymbolAddress((void**)&vb,  g_vb);
    cudaGetSymbolAddress((void**)&gb,  g_gb);
    cudaGetSymbolAddress((void**)&pb,  g_pb);
    cudaGetSymbolAddress((void**)&s,   g_s);

    const int M = NB * NL;      // 16384
    const long long WSZ = 512 * 512;

    cudaFuncSetAttribute(proj_k, cudaFuncAttributeMaxDynamicSharedMemorySize, DSM_NT);
    cudaFuncSetAttribute(qk_k,   cudaFuncAttributeMaxDynamicSharedMemorySize, DSM_NT);
    cudaFuncSetAttribute(pv_k,   cudaFuncAttributeMaxDynamicSharedMemorySize, DSM_NN);

    // Conversions: 2 launches (inputs z=2, weights z=8)
    {
        dim3 gi(BLD/4/256, 1, 2);
        f2bf_in_k<<<gi, 256>>>((const float4*)h_s, (const float4*)h_c, (uint2*)hbf);
        WPtrs wp;
        for (int i = 0; i < 8; i++) wp.W[i] = (const float4*)W[i];
        dim3 gw(WSZ/4/256, 1, 8);
        f2bf_w_k<<<gw, 256>>>(wp, (uint2*)wbf);
    }

    const unsigned short* hsb = hbf;
    const unsigned short* hcb = hbf + BLD;

    // Phase 1: all 8 projections in ONE launch (grid.z selects)
    {
        ProjArgs pa;
        const unsigned short* As[8] = { hsb, hcb, hcb, hsb, hcb, hsb, hsb, hcb };
        const int widx[8]           = {  0,   1,   2,   6,   3,   4,   5,   7 };
        unsigned short* Cs[8] = { qb, kb, vb, gb, qb+BLD, kb+BLD, vb+BLD, gb+BLD };
        for (int i = 0; i < 8; i++) {
            pa.A[i]    = As[i];
            pa.W[i]    = wbf + (long long)widx[i] * WSZ;
            pa.bias[i] = bia[widx[i]];
            pa.C[i]    = Cs[i];
        }
        dim3 gp(ND/128, M/128, 8), blk(128);
        proj_k<<<gp, blk, DSM_NT>>>(pa);
    }

    // Phase 2a: scores = alpha * Q @ K^T (NT, fp16 out), one launch z=16
    {
        const float alpha = 1.0f / sqrtf((float)ND);
        dim3 gq(NL/128, NL/128, 16), blk(128);
        qk_k<<<gq, blk, DSM_NT>>>(qb, kb, s, alpha);
    }

    // Phase 2b: softmax fp16 -> bf16 probs (32768 rows)
    softmax_k<<<16*NL, 256>>>((const uint4*)s, (uint4*)pb);

    // Phase 2c+3 fused: out = h + sigmoid(g) * (P @ V), one launch z=16
    {
        dim3 gc(ND/128, NL/128, 16), blk(128);
        pv_k<<<gc, blk, DSM_NN>>>(pb, vb, h_s, h_c, gb, out);
    }
}

// round 14
// speedup vs baseline: 1.0819x; 1.0085x over previous
#include <cuda_runtime.h>
#include <cuda_bf16.h>
#include <cuda_fp16.h>
#include <math.h>

// Problem constants
#define NB 8
#define NL 2048
#define ND 512
#define BLD (NB*NL*ND)              // 8,388,608 elems per tensor
#define BLL_ ((long long)NB*NL*NL)  // 33,554,432 per direction score matrix

// Scratch (device globals: allocation-free per harness rules)
__device__ unsigned short g_hbf[2ULL*BLD];        // h_s, h_c bf16
__device__ unsigned short g_wbf[8ULL*512*512];    // weights bf16
__device__ unsigned short g_qb[2ULL*BLD];
__device__ unsigned short g_kb[2ULL*BLD];
__device__ unsigned short g_vb[2ULL*BLD];
__device__ unsigned short g_gb[2ULL*BLD];
__device__ unsigned short g_s [2ULL*BLL_];        // fp16 scores
__device__ unsigned short g_pb[2ULL*BLL_];        // bf16 probs

// ---------------------------------------------------------------------------
// PTX helpers (sm_90-era, compile on plain sm_103 target)
// ---------------------------------------------------------------------------
__device__ __forceinline__ unsigned smem_u32(const void* p) {
    return (unsigned)__cvta_generic_to_shared(p);
}
__device__ __forceinline__ void cp16(unsigned dst, const void* src) {
    asm volatile("cp.async.cg.shared.global [%0], [%1], 16;\n" :: "r"(dst), "l"(src));
}
__device__ __forceinline__ void cp_commit() { asm volatile("cp.async.commit_group;\n"); }
template<int N> __device__ __forceinline__ void cp_wait() {
    asm volatile("cp.async.wait_group %0;\n" :: "n"(N));
}
__device__ __forceinline__ void ldsm4(unsigned* r, unsigned a) {
    asm volatile("ldmatrix.sync.aligned.m8n8.x4.shared.b16 {%0,%1,%2,%3}, [%4];\n"
        : "=r"(r[0]), "=r"(r[1]), "=r"(r[2]), "=r"(r[3]) : "r"(a));
}
__device__ __forceinline__ void ldsm4t(unsigned* r, unsigned a) {
    asm volatile("ldmatrix.sync.aligned.m8n8.x4.trans.shared.b16 {%0,%1,%2,%3}, [%4];\n"
        : "=r"(r[0]), "=r"(r[1]), "=r"(r[2]), "=r"(r[3]) : "r"(a));
}
__device__ __forceinline__ void mma16816(float* c, const unsigned* a, const unsigned* b) {
    asm volatile("mma.sync.aligned.m16n8k16.row.col.f32.bf16.bf16.f32 "
        "{%0,%1,%2,%3}, {%4,%5,%6,%7}, {%8,%9}, {%0,%1,%2,%3};\n"
        : "+f"(c[0]), "+f"(c[1]), "+f"(c[2]), "+f"(c[3])
        : "r"(a[0]), "r"(a[1]), "r"(a[2]), "r"(a[3]), "r"(b[0]), "r"(b[1]));
}
__device__ __forceinline__ unsigned short f2bfu(float x) {
    return __bfloat16_as_ushort(__float2bfloat16_rn(x));
}
__device__ __forceinline__ float bfu2f(unsigned short u) {
    return __bfloat162float(__ushort_as_bfloat16(u));
}

// ---------------------------------------------------------------------------
// bf16 tensor-core GEMM body (mma.sync), fp32 accumulate. Pointers pre-offset.
//   BT = true : C[m,n] = alpha*sum_k A[m,k]*B[n,k] (+bias[n])  "NT", B is NxK
//   BT = false: C[m,n] = alpha*sum_k A[m,k]*B[k,n]             "NN", B is KxN
//   OUT: 1=bf16, 2=f16, 3=fused finalize: out = H + sigmoid(G)*acc (f32)
// CTA tile 128x128x32, 128 threads = 4 warps (2x2), warp tile 64x64.
// 3-stage cp.async ring, ONE __syncthreads per 32-k slab, 3 CTAs/SM.
// LDSM and MMA interleaved within each microstep (volatile order preserved)
// so the smem crossbar and tensor pipe run concurrently.
// ---------------------------------------------------------------------------
template<bool BT, int OUT>
__device__ __forceinline__ void gemm_body(
    unsigned short* sm,
    const unsigned short* __restrict__ A,
    const unsigned short* __restrict__ Bm,
    const float* __restrict__ bias, void* __restrict__ Cv,
    int N, int K, float alpha,
    const float* __restrict__ Hres,
    const unsigned short* __restrict__ Gpre)
{
    constexpr int LDA = 40;                    // 32 + 8 pad (elems)
    constexpr int ASZ = 128 * LDA;             // 5120 elems
    constexpr int LDB = BT ? 40 : 136;         // NT: [128][40], NN: [32][136]
    constexpr int BSZ = BT ? 128 * 40 : 32 * 136;
    constexpr int STG = ASZ + BSZ;             // elems per stage

    const int tid  = threadIdx.x;
    const int lane = tid & 31;
    const int wid  = tid >> 5;
    const int warpM = wid >> 1;                // 0..1 (64 rows)
    const int warpN = wid & 1;                 // 0..1 (64 cols)
    const int rowBase = blockIdx.y * 128;
    const int colBase = blockIdx.x * 128;

    float acc[4][8][4];
    #pragma unroll
    for (int i = 0; i < 4; i++)
        #pragma unroll
        for (int j = 0; j < 8; j++)
            #pragma unroll
            for (int e = 0; e < 4; e++) acc[i][j][e] = 0.f;

    const unsigned smb = smem_u32(sm);

    auto load_stage = [&](int f) {
        const int s = f % 3;
        const int k0 = f * 32;
        const unsigned sa = smb + (unsigned)(s * STG) * 2u;
        const unsigned sb = sa + (unsigned)ASZ * 2u;
        // A: 128 rows x 32 cols, 4x16B per row, 512 chunks, 4/thread
        #pragma unroll
        for (int i = 0; i < 4; i++) {
            int c = i * 128 + tid;
            int row = c >> 2, seg = c & 3;
            cp16(sa + (unsigned)(row * LDA + seg * 8) * 2u,
                 A + (long long)(rowBase + row) * K + k0 + seg * 8);
        }
        if (BT) {  // B NxK: 128 rows x 32 cols
            #pragma unroll
            for (int i = 0; i < 4; i++) {
                int c = i * 128 + tid;
                int row = c >> 2, seg = c & 3;
                cp16(sb + (unsigned)(row * LDB + seg * 8) * 2u,
                     Bm + (long long)(colBase + row) * K + k0 + seg * 8);
            }
        } else {   // B KxN: 32 rows x 128 cols
            #pragma unroll
            for (int i = 0; i < 4; i++) {
                int c = i * 128 + tid;
                int row = c >> 4, seg = c & 15;
                cp16(sb + (unsigned)(row * LDB + seg * 8) * 2u,
                     Bm + (long long)(k0 + row) * N + colBase + seg * 8);
            }
        }
    };

    auto compute_stage = [&](int kt) {
        const int s = kt % 3;
        const unsigned sa = smb + (unsigned)(s * STG) * 2u;
        const unsigned sb = sa + (unsigned)ASZ * 2u;
        #pragma unroll
        for (int ms = 0; ms < 2; ms++) {
            const int ks = ms * 16;
            unsigned a[4][4], b[8][2];
            // A fragments for this 16-k microstep
            #pragma unroll
            for (int mi = 0; mi < 4; mi++) {
                int row = warpM * 64 + mi * 16 + (lane & 7) + (lane & 8);
                int col = ks + ((lane & 16) >> 1);
                ldsm4(a[mi], sa + (unsigned)(row * LDA + col) * 2u);
            }
            // Interleave: one B ldsm.x4 (covers ni, ni+1), then 8 MMAs.
            // asm volatile preserves this order -> smem + tensor overlap.
            #pragma unroll
            for (int np = 0; np < 4; np++) {
                const int ni = np * 2;
                if (BT) {
                    int row = warpN * 64 + (ni + ((lane >> 4) & 1)) * 8 + (lane & 7);
                    int col = ks + (lane & 8);
                    ldsm4(&b[ni][0], sb + (unsigned)(row * LDB + col) * 2u);
                } else {
                    int row = ks + (lane & 15);
                    int col = warpN * 64 + (ni + ((lane >> 4) & 1)) * 8;
                    ldsm4t(&b[ni][0], sb + (unsigned)(row * LDB + col) * 2u);
                }
                #pragma unroll
                for (int mi = 0; mi < 4; mi++) {
                    mma16816(acc[mi][ni],     a[mi], b[ni]);
                    mma16816(acc[mi][ni + 1], a[mi], b[ni + 1]);
                }
            }
        }
    };

    const int nk = K / 32;

    load_stage(0); cp_commit();
    load_stage(1); cp_commit();

    for (int kt = 0; kt < nk; kt++) {
        if (kt + 2 <= nk) cp_wait<1>(); else cp_wait<0>();
        __syncthreads();
        if (kt + 2 < nk) { load_stage(kt + 2); cp_commit(); }
        compute_stage(kt);
    }

    // Epilogue
    const int rr = lane >> 2, cc = (lane & 3) << 1;
    #pragma unroll
    for (int mi = 0; mi < 4; mi++) {
        const int row0 = rowBase + warpM * 64 + mi * 16 + rr;
        #pragma unroll
        for (int ni = 0; ni < 8; ni++) {
            const int col = colBase + warpN * 64 + ni * 8 + cc;
            const long long offA = (long long)row0 * N + col;
            const long long offB = (long long)(row0 + 8) * N + col;
            if (OUT == 3) {
                float* Cf = (float*)Cv;
                float2 hA = *(const float2*)&Hres[offA];
                float2 hB = *(const float2*)&Hres[offB];
                unsigned gA = *(const unsigned*)&Gpre[offA];
                unsigned gB = *(const unsigned*)&Gpre[offB];
                float g0 = bfu2f((unsigned short)(gA & 0xffff));
                float g1 = bfu2f((unsigned short)(gA >> 16));
                float g2 = bfu2f((unsigned short)(gB & 0xffff));
                float g3 = bfu2f((unsigned short)(gB >> 16));
                float2 oA, oB;
                oA.x = hA.x + acc[mi][ni][0] / (1.f + __expf(-g0));
                oA.y = hA.y + acc[mi][ni][1] / (1.f + __expf(-g1));
                oB.x = hB.x + acc[mi][ni][2] / (1.f + __expf(-g2));
                oB.y = hB.y + acc[mi][ni][3] / (1.f + __expf(-g3));
                *(float2*)&Cf[offA] = oA;
                *(float2*)&Cf[offB] = oB;
            } else {
                float b0 = 0.f, b1 = 0.f;
                if (bias) { b0 = bias[col]; b1 = bias[col + 1]; }
                float x0 = alpha * acc[mi][ni][0] + b0;
                float x1 = alpha * acc[mi][ni][1] + b1;
                float x2 = alpha * acc[mi][ni][2] + b0;
                float x3 = alpha * acc[mi][ni][3] + b1;
                if (OUT == 1) {
                    unsigned short* Cb = (unsigned short*)Cv;
                    *(unsigned*)&Cb[offA] = (unsigned)f2bfu(x0) | ((unsigned)f2bfu(x1) << 16);
                    *(unsigned*)&Cb[offB] = (unsigned)f2bfu(x2) | ((unsigned)f2bfu(x3) << 16);
                } else {
                    unsigned short* Ch = (unsigned short*)Cv;
                    __half2 h0 = __floats2half2_rn(x0, x1);
                    __half2 h1 = __floats2half2_rn(x2, x3);
                    *(unsigned*)&Ch[offA] = *(unsigned*)&h0;
                    *(unsigned*)&Ch[offB] = *(unsigned*)&h1;
                }
            }
        }
    }
}

// Dynamic smem sizes (bytes)
#define DSM_NT ((128*40 + 128*40) * 3 * 2)   // 61440
#define DSM_NN ((128*40 + 32*136) * 3 * 2)   // 56832

// ---------------------------------------------------------------------------
// Batched kernels (one launch per phase)
// ---------------------------------------------------------------------------
struct ProjArgs {
    const unsigned short* A[8];
    const unsigned short* W[8];
    const float*          bias[8];
    unsigned short*       C[8];
};

__global__ __launch_bounds__(128, 3)
void proj_k(ProjArgs pa)
{
    extern __shared__ __align__(16) unsigned short sm[];
    const int z = blockIdx.z;
    gemm_body<true, 1>(sm, pa.A[z], pa.W[z], pa.bias[z], pa.C[z],
                       ND, ND, 1.f, nullptr, nullptr);
}

__global__ __launch_bounds__(128, 3)
void qk_k(const unsigned short* __restrict__ Q,
          const unsigned short* __restrict__ Kb,
          unsigned short* __restrict__ S, float alpha)
{
    extern __shared__ __align__(16) unsigned short sm[];
    const int z = blockIdx.z;   // 0..15
    gemm_body<true, 2>(sm,
                       Q + (long long)z * NL * ND,
                       Kb + (long long)z * NL * ND,
                       nullptr,
                       S + (long long)z * NL * NL,
                       NL, ND, alpha, nullptr, nullptr);
}

__global__ __launch_bounds__(128, 3)
void pv_k(const unsigned short* __restrict__ P,
          const unsigned short* __restrict__ V,
          const float* __restrict__ h_s, const float* __restrict__ h_c,
          const unsigned short* __restrict__ G, float* __restrict__ out)
{
    extern __shared__ __align__(16) unsigned short sm[];
    const int z = blockIdx.z;   // 0..15: 0-7 dir0 (h_s), 8-15 dir1 (h_c)
    const float* H = (z < 8) ? (h_s + (long long)z * NL * ND)
                             : (h_c + (long long)(z - 8) * NL * ND);
    gemm_body<false, 3>(sm,
                        P + (long long)z * NL * NL,
                        V + (long long)z * NL * ND,
                        nullptr,
                        out + (long long)z * NL * ND,
                        ND, NL, 1.f, H,
                        G + (long long)z * NL * ND);
}

// ---------------------------------------------------------------------------
// fp32 -> bf16 conversions, batched
// ---------------------------------------------------------------------------
__global__ void f2bf_in_k(const float4* __restrict__ a, const float4* __restrict__ b,
                          uint2* __restrict__ out)
{
    const long long i = (long long)blockIdx.x * 256 + threadIdx.x;
    const float4* in = blockIdx.z ? b : a;
    float4 v = in[i];
    uint2 o;
    o.x = (unsigned)f2bfu(v.x) | ((unsigned)f2bfu(v.y) << 16);
    o.y = (unsigned)f2bfu(v.z) | ((unsigned)f2bfu(v.w) << 16);
    out[(long long)blockIdx.z * (BLD/4) + i] = o;
}

struct WPtrs { const float4* W[8]; };

__global__ void f2bf_w_k(WPtrs wp, uint2* __restrict__ out)
{
    const int i = blockIdx.x * 256 + threadIdx.x;
    float4 v = wp.W[blockIdx.z][i];
    uint2 o;
    o.x = (unsigned)f2bfu(v.x) | ((unsigned)f2bfu(v.y) << 16);
    o.y = (unsigned)f2bfu(v.z) | ((unsigned)f2bfu(v.w) << 16);
    out[(long long)blockIdx.z * (512*512/4) + i] = o;
}

// ---------------------------------------------------------------------------
// Row softmax: fp16 scores in, bf16 probs out. One 256-thread CTA per row
// of 2048 (each thread owns 8 contiguous halves = one uint4).
// ---------------------------------------------------------------------------
__global__ void softmax_k(const uint4* __restrict__ S, uint4* __restrict__ P)
{
    const long long base = (long long)blockIdx.x * 256;
    const int tid = threadIdx.x;
    uint4 c = S[base + tid];
    float v[8];
    {
        __half2 h; float2 f;
        *(unsigned*)&h = c.x; f = __half22float2(h); v[0] = f.x; v[1] = f.y;
        *(unsigned*)&h = c.y; f = __half22float2(h); v[2] = f.x; v[3] = f.y;
        *(unsigned*)&h = c.z; f = __half22float2(h); v[4] = f.x; v[5] = f.y;
        *(unsigned*)&h = c.w; f = __half22float2(h); v[6] = f.x; v[7] = f.y;
    }
    float m = v[0];
    #pragma unroll
    for (int j = 1; j < 8; j++) m = fmaxf(m, v[j]);
    float s = 0.f;
    #pragma unroll
    for (int j = 0; j < 8; j++) s += __expf(v[j] - m);

    #pragma unroll
    for (int o = 16; o; o >>= 1) {
        float om = __shfl_xor_sync(0xffffffffu, m, o);
        float os = __shfl_xor_sync(0xffffffffu, s, o);
        float nm = fmaxf(m, om);
        s = s * __expf(m - nm) + os * __expf(om - nm);
        m = nm;
    }
    __shared__ float smx[8], ssx[8];
    if ((tid & 31) == 0) { smx[tid >> 5] = m; ssx[tid >> 5] = s; }
    __syncthreads();
    float M = smx[0], Ssum = ssx[0];
    #pragma unroll
    for (int w = 1; w < 8; w++) {
        float om = smx[w], os = ssx[w];
        float nm = fmaxf(M, om);
        Ssum = Ssum * __expf(M - nm) + os * __expf(om - nm);
        M = nm;
    }
    const float inv = 1.f / Ssum;

    unsigned short e[8];
    #pragma unroll
    for (int j = 0; j < 8; j++) e[j] = f2bfu(__expf(v[j] - M) * inv);
    uint4 o;
    o.x = (unsigned)e[0] | ((unsigned)e[1] << 16);
    o.y = (unsigned)e[2] | ((unsigned)e[3] << 16);
    o.z = (unsigned)e[4] | ((unsigned)e[5] << 16);
    o.w = (unsigned)e[6] | ((unsigned)e[7] << 16);
    P[base + tid] = o;
}

// ---------------------------------------------------------------------------
// kernel_launch
// Inputs: h_s, h_c, then (W,b) for qs, kc, vc, qc, ks, vs, gs, gc.
// ---------------------------------------------------------------------------
extern "C" void kernel_launch(void* const* d_in, const int* in_sizes, int n_in,
                              void* d_out, int out_size)
{
    (void)in_sizes; (void)n_in; (void)out_size;
    const float* h_s = (const float*)d_in[0];
    const float* h_c = (const float*)d_in[1];
    const float* W[8]; const float* bia[8];
    for (int i = 0; i < 8; i++) { W[i] = (const float*)d_in[2 + 2*i]; bia[i] = (const float*)d_in[3 + 2*i]; }
    // order: 0=qs 1=kc 2=vc 3=qc 4=ks 5=vs 6=gs 7=gc
    float* out = (float*)d_out;

    unsigned short *hbf, *wbf, *qb, *kb, *vb, *gb, *pb, *s;
    cudaGetSymbolAddress((void**)&hbf, g_hbf);
    cudaGetSymbolAddress((void**)&wbf, g_wbf);
    cudaGetSymbolAddress((void**)&qb,  g_qb);
    cudaGetSymbolAddress((void**)&kb,  g_kb);
    cudaGetSymbolAddress((void**)&vb,  g_vb);
    cudaGetSymbolAddress((void**)&gb,  g_gb);
    cudaGetSymbolAddress((void**)&pb,  g_pb);
    cudaGetSymbolAddress((void**)&s,   g_s);

    const int M = NB * NL;      // 16384
    const long long WSZ = 512 * 512;

    cudaFuncSetAttribute(proj_k, cudaFuncAttributeMaxDynamicSharedMemorySize, DSM_NT);
    cudaFuncSetAttribute(qk_k,   cudaFuncAttributeMaxDynamicSharedMemorySize, DSM_NT);
    cudaFuncSetAttribute(pv_k,   cudaFuncAttributeMaxDynamicSharedMemorySize, DSM_NN);

    // Conversions: 2 launches (inputs z=2, weights z=8)
    {
        dim3 gi(BLD/4/256, 1, 2);
        f2bf_in_k<<<gi, 256>>>((const float4*)h_s, (const float4*)h_c, (uint2*)hbf);
        WPtrs wp;
        for (int i = 0; i < 8; i++) wp.W[i] = (const float4*)W[i];
        dim3 gw(WSZ/4/256, 1, 8);
        f2bf_w_k<<<gw, 256>>>(wp, (uint2*)wbf);
    }

    const unsigned short* hsb = hbf;
    const unsigned short* hcb = hbf + BLD;

    // Phase 1: all 8 projections in ONE launch (grid.z selects)
    {
        ProjArgs pa;
        const unsigned short* As[8] = { hsb, hcb, hcb, hsb, hcb, hsb, hsb, hcb };
        const int widx[8]           = {  0,   1,   2,   6,   3,   4,   5,   7 };
        unsigned short* Cs[8] = { qb, kb, vb, gb, qb+BLD, kb+BLD, vb+BLD, gb+BLD };
        for (int i = 0; i < 8; i++) {
            pa.A[i]    = As[i];
            pa.W[i]    = wbf + (long long)widx[i] * WSZ;
            pa.bias[i] = bia[widx[i]];
            pa.C[i]    = Cs[i];
        }
        dim3 gp(ND/128, M/128, 8), blk(128);
        proj_k<<<gp, blk, DSM_NT>>>(pa);
    }

    // Phase 2a: scores = alpha * Q @ K^T (NT, fp16 out), one launch z=16
    {
        const float alpha = 1.0f / sqrtf((float)ND);
        dim3 gq(NL/128, NL/128, 16), blk(128);
        qk_k<<<gq, blk, DSM_NT>>>(qb, kb, s, alpha);
    }

    // Phase 2b: softmax fp16 -> bf16 probs (32768 rows)
    softmax_k<<<16*NL, 256>>>((const uint4*)s, (uint4*)pb);

    // Phase 2c+3 fused: out = h + sigmoid(g) * (P @ V), one launch z=16
    {
        dim3 gc(ND/128, NL/128, 16), blk(128);
        pv_k<<<gc, blk, DSM_NN>>>(pb, vb, h_s, h_c, gb, out);
    }
}

// round 15
// speedup vs baseline: 1.1382x; 1.0521x over previous
#include <cuda_runtime.h>
#include <cuda_bf16.h>
#include <cuda_fp16.h>
#include <math.h>

// Problem constants
#define NB 8
#define NL 2048
#define ND 512
#define BLD (NB*NL*ND)              // 8,388,608 elems per tensor
#define BLL_ ((long long)NB*NL*NL)  // 33,554,432 per direction score matrix

// Scratch (device globals: allocation-free per harness rules)
__device__ unsigned short g_hbf[2ULL*BLD];        // h_s, h_c fp16
__device__ unsigned short g_wbf[8ULL*512*512];    // weights fp16
__device__ unsigned short g_qb[2ULL*BLD];         // fp16 (q pre-scaled by alpha)
__device__ unsigned short g_kb[2ULL*BLD];
__device__ unsigned short g_vb[2ULL*BLD];
__device__ unsigned short g_gb[2ULL*BLD];
__device__ unsigned short g_s [2ULL*BLL_];        // fp16 scores
__device__ unsigned short g_pb[2ULL*BLL_];        // fp16 probs

// ---------------------------------------------------------------------------
// PTX helpers (sm_90-era, compile on plain sm_103 target)
// ---------------------------------------------------------------------------
__device__ __forceinline__ unsigned smem_u32(const void* p) {
    return (unsigned)__cvta_generic_to_shared(p);
}
__device__ __forceinline__ void cp16(unsigned dst, const void* src) {
    asm volatile("cp.async.cg.shared.global [%0], [%1], 16;\n" :: "r"(dst), "l"(src));
}
__device__ __forceinline__ void cp_commit() { asm volatile("cp.async.commit_group;\n"); }
template<int N> __device__ __forceinline__ void cp_wait() {
    asm volatile("cp.async.wait_group %0;\n" :: "n"(N));
}
__device__ __forceinline__ void ldsm4(unsigned* r, unsigned a) {
    asm volatile("ldmatrix.sync.aligned.m8n8.x4.shared.b16 {%0,%1,%2,%3}, [%4];\n"
        : "=r"(r[0]), "=r"(r[1]), "=r"(r[2]), "=r"(r[3]) : "r"(a));
}
__device__ __forceinline__ void ldsm4t(unsigned* r, unsigned a) {
    asm volatile("ldmatrix.sync.aligned.m8n8.x4.trans.shared.b16 {%0,%1,%2,%3}, [%4];\n"
        : "=r"(r[0]), "=r"(r[1]), "=r"(r[2]), "=r"(r[3]) : "r"(a));
}
// fp16 inputs, fp32 accumulator (PV path)
__device__ __forceinline__ void mma16816f(float* c, const unsigned* a, const unsigned* b) {
    asm volatile("mma.sync.aligned.m16n8k16.row.col.f32.f16.f16.f32 "
        "{%0,%1,%2,%3}, {%4,%5,%6,%7}, {%8,%9}, {%0,%1,%2,%3};\n"
        : "+f"(c[0]), "+f"(c[1]), "+f"(c[2]), "+f"(c[3])
        : "r"(a[0]), "r"(a[1]), "r"(a[2]), "r"(a[3]), "r"(b[0]), "r"(b[1]));
}
// fp16 inputs, fp16 accumulator (proj/QK path — full-rate hypothesis)
__device__ __forceinline__ void mma16816h(unsigned* c, const unsigned* a, const unsigned* b) {
    asm volatile("mma.sync.aligned.m16n8k16.row.col.f16.f16.f16.f16 "
        "{%0,%1}, {%2,%3,%4,%5}, {%6,%7}, {%0,%1};\n"
        : "+r"(c[0]), "+r"(c[1])
        : "r"(a[0]), "r"(a[1]), "r"(a[2]), "r"(a[3]), "r"(b[0]), "r"(b[1]));
}
__device__ __forceinline__ unsigned short f2hu(float x) {
    return __half_as_ushort(__float2half_rn(x));
}
__device__ __forceinline__ unsigned packh2(float x, float y) {
    __half2 h = __floats2half2_rn(x, y);
    return *(unsigned*)&h;
}

// ---------------------------------------------------------------------------
// fp16 tensor-core GEMM body (mma.sync). Pointers pre-offset.
//   BT = true : C[m,n] = alpha*sum_k A[m,k]*B[n,k] (+bias[n])  "NT", B is NxK
//   BT = false: C[m,n] = sum_k A[m,k]*B[k,n]                   "NN", B is KxN
//   OUT: 1 = fp16 out with alpha*(acc+bias), f16 accumulators (proj)
//        2 = fp16 out, raw acc (QK; alpha pre-folded into Q), f16 accumulators
//        3 = fused finalize: out = H + sigmoid(G)*acc (f32), f32 accumulators
// CTA tile 128x128x32, 128 threads = 4 warps (2x2), warp tile 64x64.
// 3-stage cp.async ring, ONE __syncthreads per 32-k slab, 3 CTAs/SM.
// ---------------------------------------------------------------------------
template<bool BT, int OUT>
__device__ __forceinline__ void gemm_body(
    unsigned short* sm,
    const unsigned short* __restrict__ A,
    const unsigned short* __restrict__ Bm,
    const float* __restrict__ bias, void* __restrict__ Cv,
    int N, int K, float alpha,
    const float* __restrict__ Hres,
    const unsigned short* __restrict__ Gpre)
{
    constexpr bool F16A = (OUT != 3);
    constexpr int LDA = 40;                    // 32 + 8 pad (elems)
    constexpr int ASZ = 128 * LDA;             // 5120 elems
    constexpr int LDB = BT ? 40 : 136;         // NT: [128][40], NN: [32][136]
    constexpr int BSZ = BT ? 128 * 40 : 32 * 136;
    constexpr int STG = ASZ + BSZ;             // elems per stage

    const int tid  = threadIdx.x;
    const int lane = tid & 31;
    const int wid  = tid >> 5;
    const int warpM = wid >> 1;                // 0..1 (64 rows)
    const int warpN = wid & 1;                 // 0..1 (64 cols)
    const int rowBase = blockIdx.y * 128;
    const int colBase = blockIdx.x * 128;

    float    accf[4][8][4];
    unsigned acch[4][8][2];
    if constexpr (F16A) {
        #pragma unroll
        for (int i = 0; i < 4; i++)
            #pragma unroll
            for (int j = 0; j < 8; j++) { acch[i][j][0] = 0u; acch[i][j][1] = 0u; }
    } else {
        #pragma unroll
        for (int i = 0; i < 4; i++)
            #pragma unroll
            for (int j = 0; j < 8; j++)
                #pragma unroll
                for (int e = 0; e < 4; e++) accf[i][j][e] = 0.f;
    }

    const unsigned smb = smem_u32(sm);

    auto load_stage = [&](int f) {
        const int s = f % 3;
        const int k0 = f * 32;
        const unsigned sa = smb + (unsigned)(s * STG) * 2u;
        const unsigned sb = sa + (unsigned)ASZ * 2u;
        #pragma unroll
        for (int i = 0; i < 4; i++) {
            int c = i * 128 + tid;
            int row = c >> 2, seg = c & 3;
            cp16(sa + (unsigned)(row * LDA + seg * 8) * 2u,
                 A + (long long)(rowBase + row) * K + k0 + seg * 8);
        }
        if (BT) {  // B NxK: 128 rows x 32 cols
            #pragma unroll
            for (int i = 0; i < 4; i++) {
                int c = i * 128 + tid;
                int row = c >> 2, seg = c & 3;
                cp16(sb + (unsigned)(row * LDB + seg * 8) * 2u,
                     Bm + (long long)(colBase + row) * K + k0 + seg * 8);
            }
        } else {   // B KxN: 32 rows x 128 cols
            #pragma unroll
            for (int i = 0; i < 4; i++) {
                int c = i * 128 + tid;
                int row = c >> 4, seg = c & 15;
                cp16(sb + (unsigned)(row * LDB + seg * 8) * 2u,
                     Bm + (long long)(k0 + row) * N + colBase + seg * 8);
            }
        }
    };

    auto compute_stage = [&](int kt) {
        const int s = kt % 3;
        const unsigned sa = smb + (unsigned)(s * STG) * 2u;
        const unsigned sb = sa + (unsigned)ASZ * 2u;
        #pragma unroll
        for (int ms = 0; ms < 2; ms++) {
            const int ks = ms * 16;
            unsigned a[4][4], b[8][2];
            #pragma unroll
            for (int mi = 0; mi < 4; mi++) {
                int row = warpM * 64 + mi * 16 + (lane & 7) + (lane & 8);
                int col = ks + ((lane & 16) >> 1);
                ldsm4(a[mi], sa + (unsigned)(row * LDA + col) * 2u);
            }
            #pragma unroll
            for (int np = 0; np < 4; np++) {
                const int ni = np * 2;
                if (BT) {
                    int row = warpN * 64 + (ni + ((lane >> 4) & 1)) * 8 + (lane & 7);
                    int col = ks + (lane & 8);
                    ldsm4(&b[ni][0], sb + (unsigned)(row * LDB + col) * 2u);
                } else {
                    int row = ks + (lane & 15);
                    int col = warpN * 64 + (ni + ((lane >> 4) & 1)) * 8;
                    ldsm4t(&b[ni][0], sb + (unsigned)(row * LDB + col) * 2u);
                }
                #pragma unroll
                for (int mi = 0; mi < 4; mi++) {
                    if constexpr (F16A) {
                        mma16816h(acch[mi][ni],     a[mi], b[ni]);
                        mma16816h(acch[mi][ni + 1], a[mi], b[ni + 1]);
                    } else {
                        mma16816f(accf[mi][ni],     a[mi], b[ni]);
                        mma16816f(accf[mi][ni + 1], a[mi], b[ni + 1]);
                    }
                }
            }
        }
    };

    const int nk = K / 32;

    load_stage(0); cp_commit();
    load_stage(1); cp_commit();

    for (int kt = 0; kt < nk; kt++) {
        if (kt + 2 <= nk) cp_wait<1>(); else cp_wait<0>();
        __syncthreads();
        if (kt + 2 < nk) { load_stage(kt + 2); cp_commit(); }
        compute_stage(kt);
    }

    // Epilogue
    const int rr = lane >> 2, cc = (lane & 3) << 1;
    #pragma unroll
    for (int mi = 0; mi < 4; mi++) {
        const int row0 = rowBase + warpM * 64 + mi * 16 + rr;
        #pragma unroll
        for (int ni = 0; ni < 8; ni++) {
            const int col = colBase + warpN * 64 + ni * 8 + cc;
            const long long offA = (long long)row0 * N + col;
            const long long offB = (long long)(row0 + 8) * N + col;
            if constexpr (OUT == 3) {
                float* Cf = (float*)Cv;
                float2 hA = *(const float2*)&Hres[offA];
                float2 hB = *(const float2*)&Hres[offB];
                __half2 gA = *(const __half2*)&Gpre[offA];
                __half2 gB = *(const __half2*)&Gpre[offB];
                float2 gAf = __half22float2(gA);
                float2 gBf = __half22float2(gB);
                float2 oA, oB;
                oA.x = hA.x + accf[mi][ni][0] / (1.f + __expf(-gAf.x));
                oA.y = hA.y + accf[mi][ni][1] / (1.f + __expf(-gAf.y));
                oB.x = hB.x + accf[mi][ni][2] / (1.f + __expf(-gBf.x));
                oB.y = hB.y + accf[mi][ni][3] / (1.f + __expf(-gBf.y));
                *(float2*)&Cf[offA] = oA;
                *(float2*)&Cf[offB] = oB;
            } else if constexpr (OUT == 2) {
                // QK: raw f16 acc (alpha folded into Q projection)
                unsigned short* Ch = (unsigned short*)Cv;
                *(unsigned*)&Ch[offA] = acch[mi][ni][0];
                *(unsigned*)&Ch[offB] = acch[mi][ni][1];
            } else {
                // proj: out = alpha * (acc + bias), fp16 store
                float b0 = bias ? bias[col] : 0.f;
                float b1 = bias ? bias[col + 1] : 0.f;
                float2 f0 = __half22float2(*(__half2*)&acch[mi][ni][0]);
                float2 f1 = __half22float2(*(__half2*)&acch[mi][ni][1]);
                unsigned short* Ch = (unsigned short*)Cv;
                *(unsigned*)&Ch[offA] = packh2(alpha * (f0.x + b0), alpha * (f0.y + b1));
                *(unsigned*)&Ch[offB] = packh2(alpha * (f1.x + b0), alpha * (f1.y + b1));
            }
        }
    }
}

// Dynamic smem sizes (bytes)
#define DSM_NT ((128*40 + 128*40) * 3 * 2)   // 61440
#define DSM_NN ((128*40 + 32*136) * 3 * 2)   // 56832

// ---------------------------------------------------------------------------
// Batched kernels (one launch per phase)
// ---------------------------------------------------------------------------
struct ProjArgs {
    const unsigned short* A[8];
    const unsigned short* W[8];
    const float*          bias[8];
    unsigned short*       C[8];
    float                 alpha[8];
};

__global__ __launch_bounds__(128, 3)
void proj_k(ProjArgs pa)
{
    extern __shared__ __align__(16) unsigned short sm[];
    const int z = blockIdx.z;
    gemm_body<true, 1>(sm, pa.A[z], pa.W[z], pa.bias[z], pa.C[z],
                       ND, ND, pa.alpha[z], nullptr, nullptr);
}

__global__ __launch_bounds__(128, 3)
void qk_k(const unsigned short* __restrict__ Q,
          const unsigned short* __restrict__ Kb,
          unsigned short* __restrict__ S)
{
    extern __shared__ __align__(16) unsigned short sm[];
    const int z = blockIdx.z;   // 0..15
    gemm_body<true, 2>(sm,
                       Q + (long long)z * NL * ND,
                       Kb + (long long)z * NL * ND,
                       nullptr,
                       S + (long long)z * NL * NL,
                       NL, ND, 1.f, nullptr, nullptr);
}

__global__ __launch_bounds__(128, 3)
void pv_k(const unsigned short* __restrict__ P,
          const unsigned short* __restrict__ V,
          const float* __restrict__ h_s, const float* __restrict__ h_c,
          const unsigned short* __restrict__ G, float* __restrict__ out)
{
    extern __shared__ __align__(16) unsigned short sm[];
    const int z = blockIdx.z;   // 0..15: 0-7 dir0 (h_s), 8-15 dir1 (h_c)
    const float* H = (z < 8) ? (h_s + (long long)z * NL * ND)
                             : (h_c + (long long)(z - 8) * NL * ND);
    gemm_body<false, 3>(sm,
                        P + (long long)z * NL * NL,
                        V + (long long)z * NL * ND,
                        nullptr,
                        out + (long long)z * NL * ND,
                        ND, NL, 1.f, H,
                        G + (long long)z * NL * ND);
}

// ---------------------------------------------------------------------------
// fp32 -> fp16 conversions, batched
// ---------------------------------------------------------------------------
__global__ void f2h_in_k(const float4* __restrict__ a, const float4* __restrict__ b,
                         uint2* __restrict__ out)
{
    const long long i = (long long)blockIdx.x * 256 + threadIdx.x;
    const float4* in = blockIdx.z ? b : a;
    float4 v = in[i];
    uint2 o;
    o.x = packh2(v.x, v.y);
    o.y = packh2(v.z, v.w);
    out[(long long)blockIdx.z * (BLD/4) + i] = o;
}

struct WPtrs { const float4* W[8]; };

__global__ void f2h_w_k(WPtrs wp, uint2* __restrict__ out)
{
    const int i = blockIdx.x * 256 + threadIdx.x;
    float4 v = wp.W[blockIdx.z][i];
    uint2 o;
    o.x = packh2(v.x, v.y);
    o.y = packh2(v.z, v.w);
    out[(long long)blockIdx.z * (512*512/4) + i] = o;
}

// ---------------------------------------------------------------------------
// Row softmax: fp16 scores in, fp16 probs out. One 256-thread CTA per row
// of 2048 (each thread owns 8 contiguous halves = one uint4).
// ---------------------------------------------------------------------------
__global__ void softmax_k(const uint4* __restrict__ S, uint4* __restrict__ P)
{
    const long long base = (long long)blockIdx.x * 256;
    const int tid = threadIdx.x;
    uint4 c = S[base + tid];
    float v[8];
    {
        __half2 h; float2 f;
        *(unsigned*)&h = c.x; f = __half22float2(h); v[0] = f.x; v[1] = f.y;
        *(unsigned*)&h = c.y; f = __half22float2(h); v[2] = f.x; v[3] = f.y;
        *(unsigned*)&h = c.z; f = __half22float2(h); v[4] = f.x; v[5] = f.y;
        *(unsigned*)&h = c.w; f = __half22float2(h); v[6] = f.x; v[7] = f.y;
    }
    float m = v[0];
    #pragma unroll
    for (int j = 1; j < 8; j++) m = fmaxf(m, v[j]);
    float s = 0.f;
    #pragma unroll
    for (int j = 0; j < 8; j++) s += __expf(v[j] - m);

    #pragma unroll
    for (int o = 16; o; o >>= 1) {
        float om = __shfl_xor_sync(0xffffffffu, m, o);
        float os = __shfl_xor_sync(0xffffffffu, s, o);
        float nm = fmaxf(m, om);
        s = s * __expf(m - nm) + os * __expf(om - nm);
        m = nm;
    }
    __shared__ float smx[8], ssx[8];
    if ((tid & 31) == 0) { smx[tid >> 5] = m; ssx[tid >> 5] = s; }
    __syncthreads();
    float M = smx[0], Ssum = ssx[0];
    #pragma unroll
    for (int w = 1; w < 8; w++) {
        float om = smx[w], os = ssx[w];
        float nm = fmaxf(M, om);
        Ssum = Ssum * __expf(M - nm) + os * __expf(om - nm);
        M = nm;
    }
    const float inv = 1.f / Ssum;

    float e[8];
    #pragma unroll
    for (int j = 0; j < 8; j++) e[j] = __expf(v[j] - M) * inv;
    uint4 o;
    o.x = packh2(e[0], e[1]);
    o.y = packh2(e[2], e[3]);
    o.z = packh2(e[4], e[5]);
    o.w = packh2(e[6], e[7]);
    P[base + tid] = o;
}

// ---------------------------------------------------------------------------
// kernel_launch
// Inputs: h_s, h_c, then (W,b) for qs, kc, vc, qc, ks, vs, gs, gc.
// ---------------------------------------------------------------------------
extern "C" void kernel_launch(void* const* d_in, const int* in_sizes, int n_in,
                              void* d_out, int out_size)
{
    (void)in_sizes; (void)n_in; (void)out_size;
    const float* h_s = (const float*)d_in[0];
    const float* h_c = (const float*)d_in[1];
    const float* W[8]; const float* bia[8];
    for (int i = 0; i < 8; i++) { W[i] = (const float*)d_in[2 + 2*i]; bia[i] = (const float*)d_in[3 + 2*i]; }
    // order: 0=qs 1=kc 2=vc 3=qc 4=ks 5=vs 6=gs 7=gc
    float* out = (float*)d_out;

    unsigned short *hbf, *wbf, *qb, *kb, *vb, *gb, *pb, *s;
    cudaGetSymbolAddress((void**)&hbf, g_hbf);
    cudaGetSymbolAddress((void**)&wbf, g_wbf);
    cudaGetSymbolAddress((void**)&qb,  g_qb);
    cudaGetSymbolAddress((void**)&kb,  g_kb);
    cudaGetSymbolAddress((void**)&vb,  g_vb);
    cudaGetSymbolAddress((void**)&gb,  g_gb);
    cudaGetSymbolAddress((void**)&pb,  g_pb);
    cudaGetSymbolAddress((void**)&s,   g_s);

    const int M = NB * NL;      // 16384
    const long long WSZ = 512 * 512;
    const float alpha = 1.0f / sqrtf((float)ND);

    cudaFuncSetAttribute(proj_k, cudaFuncAttributeMaxDynamicSharedMemorySize, DSM_NT);
    cudaFuncSetAttribute(qk_k,   cudaFuncAttributeMaxDynamicSharedMemorySize, DSM_NT);
    cudaFuncSetAttribute(pv_k,   cudaFuncAttributeMaxDynamicSharedMemorySize, DSM_NN);

    // Conversions: 2 launches (inputs z=2, weights z=8)
    {
        dim3 gi(BLD/4/256, 1, 2);
        f2h_in_k<<<gi, 256>>>((const float4*)h_s, (const float4*)h_c, (uint2*)hbf);
        WPtrs wp;
        for (int i = 0; i < 8; i++) wp.W[i] = (const float4*)W[i];
        dim3 gw(WSZ/4/256, 1, 8);
        f2h_w_k<<<gw, 256>>>(wp, (uint2*)wbf);
    }

    const unsigned short* hsb = hbf;
    const unsigned short* hcb = hbf + BLD;

    // Phase 1: all 8 projections in ONE launch (grid.z selects).
    // Q projections (z=0 for dir0, z=4 for dir1) fold in alpha.
    {
        ProjArgs pa;
        const unsigned short* As[8] = { hsb, hcb, hcb, hsb, hcb, hsb, hsb, hcb };
        const int widx[8]           = {  0,   1,   2,   6,   3,   4,   5,   7 };
        unsigned short* Cs[8] = { qb, kb, vb, gb, qb+BLD, kb+BLD, vb+BLD, gb+BLD };
        for (int i = 0; i < 8; i++) {
            pa.A[i]    = As[i];
            pa.W[i]    = wbf + (long long)widx[i] * WSZ;
            pa.bias[i] = bia[widx[i]];
            pa.C[i]    = Cs[i];
            pa.alpha[i] = (i == 0 || i == 4) ? alpha : 1.f;
        }
        dim3 gp(ND/128, M/128, 8), blk(128);
        proj_k<<<gp, blk, DSM_NT>>>(pa);
    }

    // Phase 2a: scores = (alpha*Q) @ K^T (NT, fp16 acc + out), one launch z=16
    {
        dim3 gq(NL/128, NL/128, 16), blk(128);
        qk_k<<<gq, blk, DSM_NT>>>(qb, kb, s);
    }

    // Phase 2b: softmax fp16 -> fp16 probs (32768 rows)
    softmax_k<<<16*NL, 256>>>((const uint4*)s, (uint4*)pb);

    // Phase 2c+3 fused: out = h + sigmoid(g) * (P @ V), f32 acc, one launch z=16
    {
        dim3 gc(ND/128, NL/128, 16), blk(128);
        pv_k<<<gc, blk, DSM_NN>>>(pb, vb, h_s, h_c, gb, out);
    }
}